// round 9
// baseline (speedup 1.0000x reference)
#include <cuda_runtime.h>
#include <cuda_bf16.h>
#include <cstdint>

// ---------------------------------------------------------------------------
// Nystrom attention transformer layer. TF32 mma GEMMs, 64x64 warp tiles,
// cp.async pipelines, conflict-free smem. a1 never materialized:
// sim1+softmax+(@W) fused straight into ctx.
// ---------------------------------------------------------------------------

#define B_    4
#define N_    4096
#define DIM_  512
#define H_    8
#define DH_   64
#define M_    256
#define L_    16
#define ROWS_ (B_ * N_)          // 16384
#define BH_   (B_ * H_)          // 32

// ---------------- scratch (device globals) ----------------------------------
__device__ float g_ln  [ROWS_ * DIM_];
__device__ float g_q   [BH_ * N_ * DH_];
__device__ float g_k   [BH_ * N_ * DH_];
__device__ float g_v   [BH_ * N_ * DH_];
__device__ float g_ql  [BH_ * M_ * DH_];
__device__ float g_kl  [BH_ * M_ * DH_];
__device__ float g_a3  [BH_ * M_ * N_];     // exp(sim3)
__device__ float g_a2  [BH_ * M_ * M_];
__device__ float g_z0  [BH_ * M_ * M_];
__device__ float g_z1  [BH_ * M_ * M_];
__device__ float g_t1  [BH_ * M_ * M_];
__device__ float g_t2  [BH_ * M_ * M_];
__device__ float g_t3  [BH_ * M_ * M_];
__device__ float g_a3v [BH_ * M_ * DH_];
__device__ float g_wt  [BH_ * DH_ * M_];    // (a2inv @ a3v)^T : [bh][d][m]
__device__ float g_part[BH_ * 4 * M_ * DH_];
__device__ float g_rsum[BH_ * M_];
__device__ float g_ctx [ROWS_ * DIM_];
__device__ float g_max [2];

// ---------------- reductions -------------------------------------------------
__device__ __forceinline__ float blockReduceSum(float v, float* sh) {
    int tid = threadIdx.x;
    sh[tid] = v; __syncthreads();
    for (int s = 128; s > 0; s >>= 1) {
        if (tid < s) sh[tid] += sh[tid + s];
        __syncthreads();
    }
    float r = sh[0]; __syncthreads();
    return r;
}
__device__ __forceinline__ float blockReduceMax(float v, float* sh) {
    int tid = threadIdx.x;
    sh[tid] = v; __syncthreads();
    for (int s = 128; s > 0; s >>= 1) {
        if (tid < s) sh[tid] = fmaxf(sh[tid], sh[tid + s]);
        __syncthreads();
    }
    float r = sh[0]; __syncthreads();
    return r;
}

// ---------------- layernorm --------------------------------------------------
__global__ __launch_bounds__(256) void ln_kernel(
    const float* __restrict__ x, const float* __restrict__ w,
    const float* __restrict__ b)
{
    __shared__ float sh[256];
    long long r = blockIdx.x;
    const float* xr = x + r * DIM_;
    int tid = threadIdx.x;
    float v0 = xr[tid], v1 = xr[tid + 256];
    float s = blockReduceSum(v0 + v1, sh);
    float mu = s * (1.0f / DIM_);
    float d0 = v0 - mu, d1 = v1 - mu;
    float s2 = blockReduceSum(d0 * d0 + d1 * d1, sh);
    float inv = rsqrtf(s2 * (1.0f / DIM_) + 1e-5f);
    g_ln[r * DIM_ + tid]        = d0 * inv * w[tid] + b[tid];
    g_ln[r * DIM_ + tid + 256]  = d1 * inv * w[tid + 256] + b[tid + 256];
}

// ---------------- mma + cp.async helpers -------------------------------------
__device__ __forceinline__ void mma_tf32(
    float& c0, float& c1, float& c2, float& c3,
    uint32_t a0, uint32_t a1, uint32_t a2, uint32_t a3,
    uint32_t b0, uint32_t b1)
{
    asm volatile(
        "mma.sync.aligned.m16n8k8.row.col.f32.tf32.tf32.f32 "
        "{%0,%1,%2,%3}, {%4,%5,%6,%7}, {%8,%9}, {%0,%1,%2,%3};"
        : "+f"(c0), "+f"(c1), "+f"(c2), "+f"(c3)
        : "r"(a0), "r"(a1), "r"(a2), "r"(a3), "r"(b0), "r"(b1));
}
__device__ __forceinline__ void cpa16(void* dst, const void* src) {
    uint32_t d = (uint32_t)__cvta_generic_to_shared(dst);
    asm volatile("cp.async.cg.shared.global [%0], [%1], 16;" :: "r"(d), "l"(src));
}
#define CP_COMMIT() asm volatile("cp.async.commit_group;" ::: "memory")
#define CP_WAIT1()  asm volatile("cp.async.wait_group 1;" ::: "memory")
#define CP_WAIT0()  asm volatile("cp.async.wait_group 0;" ::: "memory")

#define BK2 16
#define RS  20      // [row][k] stride (words): frag banks 20g+tg = all 32 distinct

// ---------------- main mma GEMM: 128 threads, 2x2 warps, 64x64 warp tile -----
// BN=128: 3-stage single-sync pipeline, 2 CTAs/SM.
// BN=64 : 2-stage pipeline, 3 CTAs/SM (occupancy for small GEMMs).
// MODE 0: standard epilogue; MODE 1: qkv split; MODE 2: ctx layout;
// MODE 3: exp + atomic row sums (sim3); MODE 4: transposed output (wt).
// SPLITK: blockIdx.z = bh*4 + split, Kdim = chunk length.
template<int BM, int BN, bool TB, int MODE, bool SPLITK>
__global__ __launch_bounds__(128, (BN == 64) ? 3 : 2) void mma_gemm_kernel(
    const float* __restrict__ A, const float* __restrict__ B,
    float* __restrict__ C, int Ndim, int Kdim, int ldA, int ldB,
    long long sA, long long sB, long long sC,
    float alpha,
    const float* __restrict__ resid, float residScale,
    const float* __restrict__ residScalePtr,
    const float* __restrict__ bias)
{
    constexpr int MT = 4;               // 64 rows / 16
    constexpr int NT = BN / 16;         // (BN/2) / 8
    constexpr int RSB = BN + 8;         // [k][n] stride: frag banks 8tg+g distinct
    constexpr int ASZ = BM * RS;
    constexpr int BSZ = TB ? BN * RS : BK2 * RSB;
    constexpr int STG = ASZ + BSZ;
    constexpr int STAGES = (BN == 64) ? 2 : 3;

    extern __shared__ __align__(16) float smp[];

    int bz = blockIdx.z;
    long long aOff, bOff, cOff;
    if (SPLITK) {
        int bz0 = bz >> 2, sp = bz & 3;
        aOff = (long long)bz0 * sA + (long long)sp * Kdim;
        bOff = (long long)bz0 * sB + (long long)sp * Kdim * ldB;
        cOff = (long long)bz * sC;
    } else {
        aOff = (long long)bz * sA;
        bOff = (long long)bz * sB;
        cOff = (long long)bz * sC;
    }
    const float* Ab = A + aOff;
    const float* Bb = B + bOff;
    float*       Cb = C + cOff;
    const float* Rb = resid ? resid + cOff : nullptr;

    int n0 = blockIdx.x * BN;
    int m0 = blockIdx.y * BM;
    int tid  = threadIdx.x;
    int wid  = tid >> 5;
    int lane = tid & 31;
    int wm = wid >> 1, wn = wid & 1;
    int tm0 = wm * 64, tn0 = wn * (BN / 2);
    int g  = lane >> 2;
    int tg = lane & 3;

    float acc[MT][NT][4];
    #pragma unroll
    for (int i = 0; i < MT; i++)
        #pragma unroll
        for (int j = 0; j < NT; j++)
            #pragma unroll
            for (int c = 0; c < 4; c++) acc[i][j][c] = 0.f;

    auto loadTile = [&](int t, int st) {
        int k0 = t * BK2;
        float* As = smp + st * STG;
        float* Bs = As + ASZ;
        #pragma unroll
        for (int c = 0; c < BM / 32; c++) {
            int id = c * 128 + tid;
            int m = id >> 2, kq = (id & 3) * 4;
            cpa16(&As[m * RS + kq],
                  Ab + (long long)(m0 + m) * ldA + k0 + kq);
        }
        if (TB) {
            #pragma unroll
            for (int c = 0; c < BN / 32; c++) {
                int id = c * 128 + tid;
                int n = id >> 2, kq = (id & 3) * 4;
                cpa16(&Bs[n * RS + kq],
                      Bb + (long long)(n0 + n) * ldB + k0 + kq);
            }
        } else {
            constexpr int CPR = BN / 4;   // 16B chunks per k-row
            #pragma unroll
            for (int c = 0; c < BN / 32; c++) {
                int id = c * 128 + tid;
                int k = id / CPR, nq = (id % CPR) * 4;
                cpa16(&Bs[k * RSB + nq],
                      Bb + (long long)(k0 + k) * ldB + n0 + nq);
            }
        }
    };

    auto computeStage = [&](int st) {
        const float* as = smp + st * STG;
        const float* bs = as + ASZ;
        #pragma unroll
        for (int kk = 0; kk < BK2; kk += 8) {
            int c0 = kk + tg, c1 = c0 + 4;
            uint32_t af[MT][4], bf[NT][2];
            #pragma unroll
            for (int i = 0; i < MT; i++) {
                int r0 = (tm0 + i * 16 + g) * RS;
                int r1 = r0 + 8 * RS;
                af[i][0] = __float_as_uint(as[r0 + c0]);
                af[i][1] = __float_as_uint(as[r1 + c0]);
                af[i][2] = __float_as_uint(as[r0 + c1]);
                af[i][3] = __float_as_uint(as[r1 + c1]);
            }
            #pragma unroll
            for (int j = 0; j < NT; j++) {
                if (TB) {
                    int rn = (tn0 + j * 8 + g) * RS;
                    bf[j][0] = __float_as_uint(bs[rn + c0]);
                    bf[j][1] = __float_as_uint(bs[rn + c1]);
                } else {
                    int b0 = c0 * RSB + tn0 + j * 8 + g;
                    bf[j][0] = __float_as_uint(bs[b0]);
                    bf[j][1] = __float_as_uint(bs[b0 + 4 * RSB]);
                }
            }
            #pragma unroll
            for (int i = 0; i < MT; i++)
                #pragma unroll
                for (int j = 0; j < NT; j++)
                    mma_tf32(acc[i][j][0], acc[i][j][1], acc[i][j][2], acc[i][j][3],
                             af[i][0], af[i][1], af[i][2], af[i][3],
                             bf[j][0], bf[j][1]);
        }
    };

    int nIter = Kdim / BK2;
    loadTile(0, 0); CP_COMMIT();
    loadTile(1, 1); CP_COMMIT();
    int p = 0;
    if (STAGES == 3) {
        for (int t = 0; t < nIter; t++) {
            CP_WAIT1();
            __syncthreads();
            if (t + 2 < nIter) {
                int st = p + 2; if (st >= 3) st -= 3;
                loadTile(t + 2, st);
            }
            CP_COMMIT();
            computeStage(p);
            p = (p + 1 == 3) ? 0 : p + 1;
        }
    } else {
        for (int t = 0; t < nIter; t++) {
            CP_WAIT1();
            __syncthreads();
            computeStage(p);
            __syncthreads();
            if (t + 2 < nIter) loadTile(t + 2, p);
            CP_COMMIT();
            p ^= 1;
        }
    }

    // ---------------- epilogue ----------------
    if (MODE == 3) {
        #pragma unroll
        for (int i = 0; i < MT; i++) {
            int r0 = m0 + tm0 + i * 16 + g;
            int r1 = r0 + 8;
            float s0 = 0.f, s1 = 0.f;
            #pragma unroll
            for (int j = 0; j < NT; j++) {
                int cc = n0 + tn0 + j * 8 + tg * 2;
                float e0 = __expf(acc[i][j][0]);
                float e1 = __expf(acc[i][j][1]);
                float e2 = __expf(acc[i][j][2]);
                float e3 = __expf(acc[i][j][3]);
                *(float2*)(Cb + (long long)r0 * Ndim + cc) = make_float2(e0, e1);
                *(float2*)(Cb + (long long)r1 * Ndim + cc) = make_float2(e2, e3);
                s0 += e0 + e1; s1 += e2 + e3;
            }
            s0 += __shfl_xor_sync(0xffffffffu, s0, 1);
            s0 += __shfl_xor_sync(0xffffffffu, s0, 2);
            s1 += __shfl_xor_sync(0xffffffffu, s1, 1);
            s1 += __shfl_xor_sync(0xffffffffu, s1, 2);
            if (tg == 0) {
                atomicAdd(&g_rsum[bz * M_ + r0], s0);
                atomicAdd(&g_rsum[bz * M_ + r1], s1);
            }
        }
        return;
    }

    float rs = residScalePtr ? *residScalePtr : residScale;
    #pragma unroll
    for (int i = 0; i < MT; i++) {
        int r0 = m0 + tm0 + i * 16 + g;
        int r1 = r0 + 8;
        #pragma unroll
        for (int j = 0; j < NT; j++) {
            int cc = n0 + tn0 + j * 8 + tg * 2;
            if (MODE == 0) {
                float2 bv = bias ? *(const float2*)(bias + cc) : make_float2(0.f, 0.f);
                float2 v0 = make_float2(alpha * acc[i][j][0] + bv.x,
                                        alpha * acc[i][j][1] + bv.y);
                float2 v1 = make_float2(alpha * acc[i][j][2] + bv.x,
                                        alpha * acc[i][j][3] + bv.y);
                if (Rb) {
                    float2 q0 = *(const float2*)(Rb + (long long)r0 * Ndim + cc);
                    float2 q1 = *(const float2*)(Rb + (long long)r1 * Ndim + cc);
                    v0.x += rs * q0.x; v0.y += rs * q0.y;
                    v1.x += rs * q1.x; v1.y += rs * q1.y;
                }
                *(float2*)(Cb + (long long)r0 * Ndim + cc) = v0;
                *(float2*)(Cb + (long long)r1 * Ndim + cc) = v1;
            } else if (MODE == 1) {
                int which = cc >> 9;
                int hc = cc & 511;
                int h = hc >> 6, d = hc & 63;
                float sc = (which == 0) ? 0.125f : 1.0f;
                float* dstbuf = (which == 0) ? g_q : (which == 1) ? g_k : g_v;
                #pragma unroll
                for (int rr = 0; rr < 2; rr++) {
                    int row = rr ? r1 : r0;
                    int b = row >> 12, nn = row & 4095;
                    long long dst = (((long long)((b << 3) + h)) * N_ + nn) * DH_ + d;
                    float2 v = rr ? make_float2(sc * acc[i][j][2], sc * acc[i][j][3])
                                  : make_float2(sc * acc[i][j][0], sc * acc[i][j][1]);
                    *(float2*)(dstbuf + dst) = v;
                }
            } else if (MODE == 2) {
                int b = bz >> 3, h = bz & 7;
                *(float2*)(g_ctx + ((long long)(b * N_ + r0)) * DIM_ + h * DH_ + cc) =
                    make_float2(acc[i][j][0], acc[i][j][1]);
                *(float2*)(g_ctx + ((long long)(b * N_ + r1)) * DIM_ + h * DH_ + cc) =
                    make_float2(acc[i][j][2], acc[i][j][3]);
            } else {   // MODE 4: transposed store Cb[col][row], 256-row stride
                Cb[(cc + 0) * 256 + r0] = acc[i][j][0];
                Cb[(cc + 1) * 256 + r0] = acc[i][j][1];
                Cb[(cc + 0) * 256 + r1] = acc[i][j][2];
                Cb[(cc + 1) * 256 + r1] = acc[i][j][3];
            }
        }
    }
}

// ---------------- sim GEMM (TB) with fused full-row softmax (used for a2) ----
__global__ __launch_bounds__(256) void sim_softmax_kernel(
    const float* __restrict__ A, const float* __restrict__ Bm,
    float* __restrict__ C, int Kdim,
    long long sA, long long sB, long long sC)
{
    constexpr int BMs = 64;
    __shared__ __align__(16) float As[BMs * RS];
    __shared__ __align__(16) float Bs[256 * RS];
    __shared__ float redM[4][BMs];
    __shared__ float redS[4][BMs];

    int bz = blockIdx.z;
    const float* Ab = A + (long long)bz * sA;
    const float* Bb = Bm + (long long)bz * sB;
    float*       Cb = C + (long long)bz * sC;

    int m0 = blockIdx.y * BMs;
    int tid  = threadIdx.x;
    int wid  = tid >> 5;
    int lane = tid & 31;
    int wm = wid >> 2, wn = wid & 3;
    int tm0 = wm * 32, tn0 = wn * 64;
    int g  = lane >> 2;
    int tg = lane & 3;

    float acc[2][8][4];
    #pragma unroll
    for (int i = 0; i < 2; i++)
        #pragma unroll
        for (int j = 0; j < 8; j++)
            #pragma unroll
            for (int c = 0; c < 4; c++) acc[i][j][c] = 0.f;

    for (int k0 = 0; k0 < Kdim; k0 += BK2) {
        {
            int m = tid >> 2, kq = (tid & 3) * 4;
            cpa16(&As[m * RS + kq], Ab + (long long)(m0 + m) * Kdim + k0 + kq);
        }
        #pragma unroll
        for (int c = 0; c < 4; c++) {
            int id = c * 256 + tid;
            int n = id >> 2, kq = (id & 3) * 4;
            cpa16(&Bs[n * RS + kq], Bb + (long long)n * Kdim + k0 + kq);
        }
        CP_COMMIT();
        CP_WAIT0();
        __syncthreads();

        #pragma unroll
        for (int kk = 0; kk < BK2; kk += 8) {
            int c0 = kk + tg, c1 = c0 + 4;
            uint32_t af[2][4], bf[8][2];
            #pragma unroll
            for (int i = 0; i < 2; i++) {
                int r0 = (tm0 + i * 16 + g) * RS;
                int r1 = r0 + 8 * RS;
                af[i][0] = __float_as_uint(As[r0 + c0]);
                af[i][1] = __float_as_uint(As[r1 + c0]);
                af[i][2] = __float_as_uint(As[r0 + c1]);
                af[i][3] = __float_as_uint(As[r1 + c1]);
            }
            #pragma unroll
            for (int j = 0; j < 8; j++) {
                int rn = (tn0 + j * 8 + g) * RS;
                bf[j][0] = __float_as_uint(Bs[rn + c0]);
                bf[j][1] = __float_as_uint(Bs[rn + c1]);
            }
            #pragma unroll
            for (int i = 0; i < 2; i++)
                #pragma unroll
                for (int j = 0; j < 8; j++)
                    mma_tf32(acc[i][j][0], acc[i][j][1], acc[i][j][2], acc[i][j][3],
                             af[i][0], af[i][1], af[i][2], af[i][3],
                             bf[j][0], bf[j][1]);
        }
        __syncthreads();
    }

    #pragma unroll
    for (int i = 0; i < 2; i++) {
        float mx0 = -1e30f, mx1 = -1e30f;
        #pragma unroll
        for (int j = 0; j < 8; j++) {
            mx0 = fmaxf(mx0, fmaxf(acc[i][j][0], acc[i][j][1]));
            mx1 = fmaxf(mx1, fmaxf(acc[i][j][2], acc[i][j][3]));
        }
        mx0 = fmaxf(mx0, __shfl_xor_sync(0xffffffffu, mx0, 1));
        mx0 = fmaxf(mx0, __shfl_xor_sync(0xffffffffu, mx0, 2));
        mx1 = fmaxf(mx1, __shfl_xor_sync(0xffffffffu, mx1, 1));
        mx1 = fmaxf(mx1, __shfl_xor_sync(0xffffffffu, mx1, 2));
        if (tg == 0) {
            redM[wn][tm0 + i * 16 + g]     = mx0;
            redM[wn][tm0 + i * 16 + g + 8] = mx1;
        }
    }
    __syncthreads();
    #pragma unroll
    for (int i = 0; i < 2; i++) {
        int rb0 = tm0 + i * 16 + g, rb1 = rb0 + 8;
        float mx0 = fmaxf(fmaxf(redM[0][rb0], redM[1][rb0]),
                          fmaxf(redM[2][rb0], redM[3][rb0]));
        float mx1 = fmaxf(fmaxf(redM[0][rb1], redM[1][rb1]),
                          fmaxf(redM[2][rb1], redM[3][rb1]));
        float s0 = 0.f, s1 = 0.f;
        #pragma unroll
        for (int j = 0; j < 8; j++) {
            float e0 = __expf(acc[i][j][0] - mx0);
            float e1 = __expf(acc[i][j][1] - mx0);
            float e2 = __expf(acc[i][j][2] - mx1);
            float e3 = __expf(acc[i][j][3] - mx1);
            acc[i][j][0] = e0; acc[i][j][1] = e1;
            acc[i][j][2] = e2; acc[i][j][3] = e3;
            s0 += e0 + e1; s1 += e2 + e3;
        }
        s0 += __shfl_xor_sync(0xffffffffu, s0, 1);
        s0 += __shfl_xor_sync(0xffffffffu, s0, 2);
        s1 += __shfl_xor_sync(0xffffffffu, s1, 1);
        s1 += __shfl_xor_sync(0xffffffffu, s1, 2);
        if (tg == 0) { redS[wn][rb0] = s0; redS[wn][rb1] = s1; }
    }
    __syncthreads();
    #pragma unroll
    for (int i = 0; i < 2; i++) {
        int rb0 = tm0 + i * 16 + g, rb1 = rb0 + 8;
        float i0 = 1.f / (redS[0][rb0] + redS[1][rb0] + redS[2][rb0] + redS[3][rb0]);
        float i1 = 1.f / (redS[0][rb1] + redS[1][rb1] + redS[2][rb1] + redS[3][rb1]);
        int r0 = m0 + rb0, r1 = m0 + rb1;
        #pragma unroll
        for (int j = 0; j < 8; j++) {
            int cc = tn0 + j * 8 + tg * 2;
            *(float2*)(Cb + (long long)r0 * 256 + cc) =
                make_float2(acc[i][j][0] * i0, acc[i][j][1] * i0);
            *(float2*)(Cb + (long long)r1 * 256 + cc) =
                make_float2(acc[i][j][2] * i1, acc[i][j][3] * i1);
        }
    }
}

// ---------------- fused sim1 + softmax + (@W) -> ctx --------------------------
// grid (1, N/64, BH), 256 threads. Dynamic smem:
//   Aw[64*260] | Bw[64*260] | As1[64*20] | Bs1[256*20]   (total 158.7 KB)
#define AW_OFF  0
#define BW_OFF  16640
#define AS1_OFF 33280
#define BS1_OFF 34560
#define SIM1_SMEM ((34560 + 5120) * 4)

__global__ __launch_bounds__(256) void sim1_ctx_kernel()
{
    extern __shared__ __align__(16) float sm[];
    float* Aw  = sm + AW_OFF;
    float* Bw  = sm + BW_OFF;
    float* As1 = sm + AS1_OFF;
    float* Bs1 = sm + BS1_OFF;
    __shared__ float redM[4][64];
    __shared__ float redS[4][64];

    int bz = blockIdx.z;
    const float* Ab = g_q  + (long long)bz * (N_ * DH_);
    const float* Bb = g_kl + (long long)bz * (M_ * DH_);
    const float* Wt = g_wt + (long long)bz * (DH_ * M_);

    int m0 = blockIdx.y * 64;
    int tid  = threadIdx.x;
    int wid  = tid >> 5;
    int lane = tid & 31;
    int wm = wid >> 2, wn = wid & 3;
    int tm0 = wm * 32, tn0 = wn * 64;
    int g  = lane >> 2;
    int tg = lane & 3;

    // prefetch Wt (64 d-rows x 256 m) into Bw, stride 260
    #pragma unroll
    for (int c = 0; c < 16; c++) {
        int id = c * 256 + tid;
        int d = id >> 6, kq = (id & 63) * 4;
        cpa16(&Bw[d * 260 + kq], Wt + d * 256 + kq);
    }
    CP_COMMIT();

    float acc[2][8][4];
    #pragma unroll
    for (int i = 0; i < 2; i++)
        #pragma unroll
        for (int j = 0; j < 8; j++)
            #pragma unroll
            for (int c = 0; c < 4; c++) acc[i][j][c] = 0.f;

    // ---- phase 1: sim1 = q @ kl^T (64 x 256, K = 64) ----
    for (int k0 = 0; k0 < DH_; k0 += BK2) {
        {
            int m = tid >> 2, kq = (tid & 3) * 4;
            cpa16(&As1[m * RS + kq], Ab + (long long)(m0 + m) * DH_ + k0 + kq);
        }
        #pragma unroll
        for (int c = 0; c < 4; c++) {
            int id = c * 256 + tid;
            int n = id >> 2, kq = (id & 3) * 4;
            cpa16(&Bs1[n * RS + kq], Bb + (long long)n * DH_ + k0 + kq);
        }
        CP_COMMIT();
        CP_WAIT0();
        __syncthreads();

        #pragma unroll
        for (int kk = 0; kk < BK2; kk += 8) {
            int c0 = kk + tg, c1 = c0 + 4;
            uint32_t af[2][4], bf[8][2];
            #pragma unroll
            for (int i = 0; i < 2; i++) {
                int r0 = (tm0 + i * 16 + g) * RS;
                int r1 = r0 + 8 * RS;
                af[i][0] = __float_as_uint(As1[r0 + c0]);
                af[i][1] = __float_as_uint(As1[r1 + c0]);
                af[i][2] = __float_as_uint(As1[r0 + c1]);
                af[i][3] = __float_as_uint(As1[r1 + c1]);
            }
            #pragma unroll
            for (int j = 0; j < 8; j++) {
                int rn = (tn0 + j * 8 + g) * RS;
                bf[j][0] = __float_as_uint(Bs1[rn + c0]);
                bf[j][1] = __float_as_uint(Bs1[rn + c1]);
            }
            #pragma unroll
            for (int i = 0; i < 2; i++)
                #pragma unroll
                for (int j = 0; j < 8; j++)
                    mma_tf32(acc[i][j][0], acc[i][j][1], acc[i][j][2], acc[i][j][3],
                             af[i][0], af[i][1], af[i][2], af[i][3],
                             bf[j][0], bf[j][1]);
        }
        __syncthreads();
    }

    // ---- softmax over full 256-wide rows (normalized into acc) ----
    #pragma unroll
    for (int i = 0; i < 2; i++) {
        float mx0 = -1e30f, mx1 = -1e30f;
        #pragma unroll
        for (int j = 0; j < 8; j++) {
            mx0 = fmaxf(mx0, fmaxf(acc[i][j][0], acc[i][j][1]));
            mx1 = fmaxf(mx1, fmaxf(acc[i][j][2], acc[i][j][3]));
        }
        mx0 = fmaxf(mx0, __shfl_xor_sync(0xffffffffu, mx0, 1));
        mx0 = fmaxf(mx0, __shfl_xor_sync(0xffffffffu, mx0, 2));
        mx1 = fmaxf(mx1, __shfl_xor_sync(0xffffffffu, mx1, 1));
        mx1 = fmaxf(mx1, __shfl_xor_sync(0xffffffffu, mx1, 2));
        if (tg == 0) {
            redM[wn][tm0 + i * 16 + g]     = mx0;
            redM[wn][tm0 + i * 16 + g + 8] = mx1;
        }
    }
    __syncthreads();
    #pragma unroll
    for (int i = 0; i < 2; i++) {
        int rb0 = tm0 + i * 16 + g, rb1 = rb0 + 8;
        float mx0 = fmaxf(fmaxf(redM[0][rb0], redM[1][rb0]),
                          fmaxf(redM[2][rb0], redM[3][rb0]));
        float mx1 = fmaxf(fmaxf(redM[0][rb1], redM[1][rb1]),
                          fmaxf(redM[2][rb1], redM[3][rb1]));
        float s0 = 0.f, s1 = 0.f;
        #pragma unroll
        for (int j = 0; j < 8; j++) {
            float e0 = __expf(acc[i][j][0] - mx0);
            float e1 = __expf(acc[i][j][1] - mx0);
            float e2 = __expf(acc[i][j][2] - mx1);
            float e3 = __expf(acc[i][j][3] - mx1);
            acc[i][j][0] = e0; acc[i][j][1] = e1;
            acc[i][j][2] = e2; acc[i][j][3] = e3;
            s0 += e0 + e1; s1 += e2 + e3;
        }
        s0 += __shfl_xor_sync(0xffffffffu, s0, 1);
        s0 += __shfl_xor_sync(0xffffffffu, s0, 2);
        s1 += __shfl_xor_sync(0xffffffffu, s1, 1);
        s1 += __shfl_xor_sync(0xffffffffu, s1, 2);
        if (tg == 0) { redS[wn][rb0] = s0; redS[wn][rb1] = s1; }
    }
    __syncthreads();
    #pragma unroll
    for (int i = 0; i < 2; i++) {
        int rb0 = tm0 + i * 16 + g, rb1 = rb0 + 8;
        float i0 = 1.f / (redS[0][rb0] + redS[1][rb0] + redS[2][rb0] + redS[3][rb0]);
        float i1 = 1.f / (redS[0][rb1] + redS[1][rb1] + redS[2][rb1] + redS[3][rb1]);
        // store normalized a1 tile into Aw ([row][k=landmark], stride 260)
        #pragma unroll
        for (int j = 0; j < 8; j++) {
            int col = tn0 + j * 8 + tg * 2;
            *(float2*)(Aw + rb0 * 260 + col) =
                make_float2(acc[i][j][0] * i0, acc[i][j][1] * i0);
            *(float2*)(Aw + rb1 * 260 + col) =
                make_float2(acc[i][j][2] * i1, acc[i][j][3] * i1);
        }
    }
    __syncthreads();

    // ---- phase 2: ctx_tile = a1_tile (64x256) @ W (256x64) ----
    // warp grid 2(m) x 4(n): warp tile 32m x 16n; MT2=2, NT2=2.
    int tn2 = wn * 16;
    float a2c[2][2][4];
    #pragma unroll
    for (int i = 0; i < 2; i++)
        #pragma unroll
        for (int j = 0; j < 2; j++)
            #pragma unroll
            for (int c = 0; c < 4; c++) a2c[i][j][c] = 0.f;

    #pragma unroll 4
    for (int kk = 0; kk < 256; kk += 8) {
        int c0 = kk + tg, c1 = c0 + 4;
        uint32_t af[2][4], bf[2][2];
        #pragma unroll
        for (int i = 0; i < 2; i++) {
            int r0 = (tm0 + i * 16 + g) * 260;
            int r1 = r0 + 8 * 260;
            af[i][0] = __float_as_uint(Aw[r0 + c0]);
            af[i][1] = __float_as_uint(Aw[r1 + c0]);
            af[i][2] = __float_as_uint(Aw[r0 + c1]);
            af[i][3] = __float_as_uint(Aw[r1 + c1]);
        }
        #pragma unroll
        for (int j = 0; j < 2; j++) {
            int rn = (tn2 + j * 8 + g) * 260;
            bf[j][0] = __float_as_uint(Bw[rn + c0]);
            bf[j][1] = __float_as_uint(Bw[rn + c1]);
        }
        #pragma unroll
        for (int i = 0; i < 2; i++)
            #pragma unroll
            for (int j = 0; j < 2; j++)
                mma_tf32(a2c[i][j][0], a2c[i][j][1], a2c[i][j][2], a2c[i][j][3],
                         af[i][0], af[i][1], af[i][2], af[i][3],
                         bf[j][0], bf[j][1]);
    }

    int b = bz >> 3, h = bz & 7;
    #pragma unroll
    for (int i = 0; i < 2; i++) {
        int row0 = m0 + tm0 + i * 16 + g;
        int row1 = row0 + 8;
        #pragma unroll
        for (int j = 0; j < 2; j++) {
            int d = tn2 + j * 8 + tg * 2;
            *(float2*)(g_ctx + ((long long)(b * N_ + row0)) * DIM_ + h * DH_ + d) =
                make_float2(a2c[i][j][0], a2c[i][j][1]);
            *(float2*)(g_ctx + ((long long)(b * N_ + row1)) * DIM_ + h * DH_ + d) =
                make_float2(a2c[i][j][2], a2c[i][j][3]);
        }
    }
}

// ---------------- landmark means ---------------------------------------------
__global__ __launch_bounds__(256) void landmark_kernel()
{
    int id = blockIdx.x * 256 + threadIdx.x;
    const int half = BH_ * M_ * DH_;
    bool isK = id >= half;
    int t = isK ? id - half : id;
    int d  = t & 63;
    int m  = (t >> 6) & 255;
    int bh = t >> 14;
    const float* src = (isK ? g_k : g_q) + ((long long)bh * N_ + m * L_) * DH_ + d;
    float s = 0.f;
    #pragma unroll
    for (int l = 0; l < L_; l++) s += src[l * DH_];
    (isK ? g_kl : g_ql)[t] = s * (1.0f / L_);
}

// ---------------- zero rsum ---------------------------------------------------
__global__ __launch_bounds__(256) void zero_rsum_kernel()
{
    g_rsum[blockIdx.x * 256 + threadIdx.x] = 0.f;
}

// ---------------- a3v split-K reduce + row normalize -------------------------
__global__ __launch_bounds__(256) void a3v_reduce_kernel()
{
    int idx = blockIdx.x * 256 + threadIdx.x;
    int rrow = idx >> 6;
    int bh = idx >> 14;
    int inner = idx & 16383;
    long long base = (long long)bh * 4 * 16384 + inner;
    float s = g_part[base] + g_part[base + 16384]
            + g_part[base + 2 * 16384] + g_part[base + 3 * 16384];
    g_a3v[idx] = s / g_rsum[rrow];
}

// ---------------- pinv init ---------------------------------------------------
__global__ void zero_max_kernel() { g_max[0] = 0.f; g_max[1] = 0.f; }

__global__ __launch_bounds__(256) void pinv_absmax_kernel()
{
    __shared__ float sh[256];
    const float* X = g_a2 + (long long)blockIdx.x * (M_ * M_);
    int tid = threadIdx.x;
    float cs = 0.f, rs = 0.f;
    for (int j = 0; j < M_; j++) cs += fabsf(X[tid * M_ + j]);
    for (int i = 0; i < M_; i++) rs += fabsf(X[i * M_ + tid]);
    float cm = blockReduceMax(cs, sh);
    float rm = blockReduceMax(rs, sh);
    if (tid == 0) {
        atomicMax(reinterpret_cast<int*>(&g_max[0]), __float_as_int(cm));
        atomicMax(reinterpret_cast<int*>(&g_max[1]), __float_as_int(rm));
    }
}

__global__ __launch_bounds__(256) void zinit_kernel()
{
    long long id = (long long)blockIdx.x * 256 + threadIdx.x;
    float inv = 1.0f / (g_max[0] * g_max[1]);
    long long bh = id >> 16;
    int rem = (int)(id & 65535);
    int row = rem >> 8, col = rem & 255;
    g_z0[id] = g_a2[bh * (M_ * M_) + (long long)col * M_ + row] * inv;
}

// ---------------- depthwise conv residual added into ctx (smem tiled) ---------
__global__ __launch_bounds__(256) void conv_add_kernel(const float* __restrict__ cw)
{
    __shared__ __align__(16) float sv[160 * 64];

    int bid = blockIdx.x;
    int bh = bid >> 5;
    int tile = bid & 31;
    int n0 = tile * 128;
    int h = bh & 7, b = bh >> 3;
    int tid = threadIdx.x;
    const float* vb = g_v + ((long long)bh << 18);

    #pragma unroll
    for (int c = 0; c < 10; c++) {
        int e = (c * 256 + tid) * 4;
        int r = e >> 6, d = e & 63;
        int gr = n0 - 16 + r;
        float4 val = make_float4(0.f, 0.f, 0.f, 0.f);
        if ((unsigned)gr < (unsigned)N_)
            val = *(const float4*)(vb + (long long)gr * DH_ + d);
        *(float4*)(sv + r * 64 + d) = val;
    }
    __syncthreads();

    int d = tid & 63, rg = tid >> 6;
    float wr[33];
    #pragma unroll
    for (int k = 0; k < 33; k++) wr[k] = cw[h * 33 + k];

    #pragma unroll
    for (int half = 0; half < 2; half++) {
        int ob = rg * 32 + half * 16;
        float in[48];
        #pragma unroll
        for (int j = 0; j < 48; j++) in[j] = sv[(ob + j) * 64 + d];
        #pragma unroll
        for (int i = 0; i < 16; i++) {
            float acc = 0.f;
            #pragma unroll
            for (int k = 0; k < 33; k++) acc += wr[k] * in[i + k];
            int grow = n0 + ob + i;
            g_ctx[((long long)(b * N_ + grow)) * DIM_ + h * DH_ + d] += acc;
        }
    }
}

// ---------------- host helpers -------------------------------------------------
static float* symaddr(const void* sym) {
    void* p = nullptr;
    cudaGetSymbolAddress(&p, sym);
    return (float*)p;
}

template<int BM, int BN, bool TB, int MODE, bool SPLITK>
static void launch_gemm(dim3 grid,
                 const float* A, const float* B, float* C,
                 int N, int K, int ldA, int ldB,
                 long long sA, long long sB, long long sC,
                 float alpha, const float* resid, float rs,
                 const float* rsPtr, const float* bias)
{
    constexpr int RSB = BN + 8;
    constexpr int ASZ = BM * RS;
    constexpr int BSZ = TB ? BN * RS : BK2 * RSB;
    constexpr int STAGES = (BN == 64) ? 2 : 3;
    int smem = STAGES * (ASZ + BSZ) * 4;
    auto kfn = mma_gemm_kernel<BM, BN, TB, MODE, SPLITK>;
    cudaFuncSetAttribute(kfn, cudaFuncAttributeMaxDynamicSharedMemorySize, smem);
    kfn<<<grid, 128, smem>>>(A, B, C, N, K, ldA, ldB, sA, sB, sC,
                             alpha, resid, rs, rsPtr, bias);
}

template<int MODE>
static void gemm(const float* A, const float* B, float* C,
                 int M, int N, int K, int batch, int ldA, int ldB,
                 long long sA, long long sB, long long sC, bool tb,
                 float alpha = 1.f,
                 const float* resid = nullptr, float rs = 0.f,
                 const float* rsPtr = nullptr,
                 const float* bias = nullptr,
                 bool forceBN64 = false)
{
    if (N % 128 == 0 && !forceBN64) {
        dim3 grid(N / 128, M / 128, batch);
        if (tb)
            launch_gemm<128, 128, true , MODE, false>(grid, A, B, C, N, K,
                ldA, ldB, sA, sB, sC, alpha, resid, rs, rsPtr, bias);
        else
            launch_gemm<128, 128, false, MODE, false>(grid, A, B, C, N, K,
                ldA, ldB, sA, sB, sC, alpha, resid, rs, rsPtr, bias);
    } else {
        dim3 grid(N / 64, M / 128, batch);
        if (tb)
            launch_gemm<128, 64, true , MODE, false>(grid, A, B, C, N, K,
                ldA, ldB, sA, sB, sC, alpha, resid, rs, rsPtr, bias);
        else
            launch_gemm<128, 64, false, MODE, false>(grid, A, B, C, N, K,
                ldA, ldB, sA, sB, sC, alpha, resid, rs, rsPtr, bias);
    }
}

extern "C" void kernel_launch(void* const* d_in, const int* in_sizes, int n_in,
                              void* d_out, int out_size)
{
    const float* x      = (const float*)d_in[0];
    const float* ln_w   = (const float*)d_in[1];
    const float* ln_b   = (const float*)d_in[2];
    const float* w_qkv  = (const float*)d_in[3];
    const float* w_out  = (const float*)d_in[4];
    const float* b_out  = (const float*)d_in[5];
    const float* conv_w = (const float*)d_in[6];
    const float* omega  = (const float*)d_in[7];
    float* out = (float*)d_out;

    float* p_ln   = symaddr(g_ln);
    float* p_q    = symaddr(g_q);
    float* p_k    = symaddr(g_k);
    float* p_ql   = symaddr(g_ql);
    float* p_kl   = symaddr(g_kl);
    float* p_a3   = symaddr(g_a3);
    float* p_a2   = symaddr(g_a2);
    float* p_z0   = symaddr(g_z0);
    float* p_z1   = symaddr(g_z1);
    float* p_t1   = symaddr(g_t1);
    float* p_t2   = symaddr(g_t2);
    float* p_t3   = symaddr(g_t3);
    float* p_a3v  = symaddr(g_a3v);
    float* p_wt   = symaddr(g_wt);
    float* p_part = symaddr(g_part);
    float* p_v    = symaddr(g_v);
    float* p_ctx  = symaddr(g_ctx);

    const long long sQ  = (long long)N_ * DH_;
    const long long sL  = (long long)M_ * DH_;
    const long long sS1 = (long long)N_ * M_;
    const long long sA2 = (long long)M_ * M_;

    // 1) layernorm
    ln_kernel<<<ROWS_, 256>>>(x, ln_w, ln_b);

    // 2) qkv projection, epilogue writes q (scaled), k, v head-major
    gemm<1>(p_ln, w_qkv, nullptr, ROWS_, 3 * DIM_, DIM_, 1, DIM_, 3 * DIM_,
            0, 0, 0, false);

    // 3) landmarks
    landmark_kernel<<<(2 * BH_ * M_ * DH_) / 256, 256>>>();

    // 4) sim2 + softmax -> a2
    sim_softmax_kernel<<<dim3(1, M_ / 64, BH_), 256>>>(
        p_ql, p_kl, p_a2, DH_, sL, sL, sA2);

    // 5) sim3 -> exp(sim3) with fused row sums
    zero_rsum_kernel<<<(BH_ * M_) / 256, 256>>>();
    gemm<3>(p_ql, p_k, p_a3, M_, N_, DH_, BH_, DH_, DH_, sL, sQ, sS1, true);

    // 6) Moore-Penrose pinv of a2 (Newton-Schulz, 6 iters), BN=64
    zero_max_kernel<<<1, 1>>>();
    pinv_absmax_kernel<<<BH_, 256>>>();
    zinit_kernel<<<(BH_ * M_ * M_) / 256, 256>>>();

    for (int it = 0; it < 6; it++) {
        float* zin  = (it & 1) ? p_z1 : p_z0;
        float* zout = (it & 1) ? p_z0 : p_z1;
        gemm<0>(p_a2, zin, p_t1, M_, M_, M_, BH_, M_, M_, sA2, sA2, sA2, false,
                1.f, nullptr, 0.f, nullptr, nullptr, true);
        gemm<0>(p_t1, p_t1, p_t2, M_, M_, M_, BH_, M_, M_, sA2, sA2, sA2, false,
                -1.f, p_t1, 7.f, nullptr, nullptr, true);
        gemm<0>(p_t1, p_t2, p_t3, M_, M_, M_, BH_, M_, M_, sA2, sA2, sA2, false,
                -1.f, p_t1, 15.f, nullptr, nullptr, true);
        gemm<0>(zin, p_t3, zout, M_, M_, M_, BH_, M_, M_, sA2, sA2, sA2, false,
                -0.25f, zin, 3.25f, nullptr, nullptr, true);
    }

    // 7) a3v = (exp(sim3) @ v) / rowsum, split-K x4
    {
        dim3 grid(1, M_ / 128, BH_ * 4);
        launch_gemm<128, 64, false, 0, true>(grid, p_a3, p_v, p_part,
            DH_, N_ / 4, N_, DH_, sS1, sQ, sL,
            1.f, nullptr, 0.f, nullptr, nullptr);
        a3v_reduce_kernel<<<(BH_ * M_ * DH_) / 256, 256>>>();
    }

    // 8) wt = (a2inv @ a3v)^T  (MODE 4 transposed epilogue)
    gemm<4>(p_z0, p_a3v, p_wt, M_, DH_, M_, BH_, M_, DH_, sA2, sL,
            (long long)DH_ * M_, false);

    // 9) fused sim1 + softmax + (@W) -> ctx  (a1 never hits HBM)
    {
        cudaFuncSetAttribute(sim1_ctx_kernel,
                             cudaFuncAttributeMaxDynamicSharedMemorySize, SIM1_SMEM);
        sim1_ctx_kernel<<<dim3(1, N_ / 64, BH_), 256, SIM1_SMEM>>>();
    }

    // 10) depthwise conv residual added into ctx (smem tiled)
    conv_add_kernel<<<BH_ * (N_ / 128), 256>>>(conv_w);

    // 11) output projection + bias + omega * x
    gemm<0>(p_ctx, w_out, out, ROWS_, DIM_, DIM_, 1, DIM_, DIM_, 0, 0, 0, false,
            1.f, x, 0.f, omega, b_out);
}

// round 10
// speedup vs baseline: 1.0230x; 1.0230x over previous
#include <cuda_runtime.h>
#include <cuda_bf16.h>
#include <cstdint>

// ---------------------------------------------------------------------------
// Nystrom attention transformer layer. TF32 mma GEMMs, 64x64 warp tiles,
// cp.async pipelines (3-stage BN=128 / 2-stage BN=64 @ 3 CTAs/SM),
// conflict-free smem, fused epilogues.
// ---------------------------------------------------------------------------

#define B_    4
#define N_    4096
#define DIM_  512
#define H_    8
#define DH_   64
#define M_    256
#define L_    16
#define ROWS_ (B_ * N_)          // 16384
#define BH_   (B_ * H_)          // 32

// ---------------- scratch (device globals) ----------------------------------
__device__ float g_ln  [ROWS_ * DIM_];
__device__ float g_q   [BH_ * N_ * DH_];
__device__ float g_k   [BH_ * N_ * DH_];
__device__ float g_v   [BH_ * N_ * DH_];
__device__ float g_ql  [BH_ * M_ * DH_];
__device__ float g_kl  [BH_ * M_ * DH_];
__device__ float g_a1  [BH_ * N_ * M_];
__device__ float g_a3  [BH_ * M_ * N_];     // exp(sim3)
__device__ float g_a2  [BH_ * M_ * M_];
__device__ float g_z0  [BH_ * M_ * M_];
__device__ float g_z1  [BH_ * M_ * M_];
__device__ float g_t1  [BH_ * M_ * M_];
__device__ float g_t2  [BH_ * M_ * M_];
__device__ float g_t3  [BH_ * M_ * M_];
__device__ float g_a3v [BH_ * M_ * DH_];
__device__ float g_w   [BH_ * M_ * DH_];    // a2inv @ a3v
__device__ float g_part[BH_ * 4 * M_ * DH_];
__device__ float g_rsum[BH_ * M_];
__device__ float g_ctx [ROWS_ * DIM_];
__device__ float g_max [2];

// ---------------- reductions -------------------------------------------------
__device__ __forceinline__ float blockReduceSum(float v, float* sh) {
    int tid = threadIdx.x;
    sh[tid] = v; __syncthreads();
    for (int s = 128; s > 0; s >>= 1) {
        if (tid < s) sh[tid] += sh[tid + s];
        __syncthreads();
    }
    float r = sh[0]; __syncthreads();
    return r;
}
__device__ __forceinline__ float blockReduceMax(float v, float* sh) {
    int tid = threadIdx.x;
    sh[tid] = v; __syncthreads();
    for (int s = 128; s > 0; s >>= 1) {
        if (tid < s) sh[tid] = fmaxf(sh[tid], sh[tid + s]);
        __syncthreads();
    }
    float r = sh[0]; __syncthreads();
    return r;
}

// ---------------- layernorm --------------------------------------------------
__global__ __launch_bounds__(256) void ln_kernel(
    const float* __restrict__ x, const float* __restrict__ w,
    const float* __restrict__ b)
{
    __shared__ float sh[256];
    long long r = blockIdx.x;
    const float* xr = x + r * DIM_;
    int tid = threadIdx.x;
    float v0 = xr[tid], v1 = xr[tid + 256];
    float s = blockReduceSum(v0 + v1, sh);
    float mu = s * (1.0f / DIM_);
    float d0 = v0 - mu, d1 = v1 - mu;
    float s2 = blockReduceSum(d0 * d0 + d1 * d1, sh);
    float inv = rsqrtf(s2 * (1.0f / DIM_) + 1e-5f);
    g_ln[r * DIM_ + tid]        = d0 * inv * w[tid] + b[tid];
    g_ln[r * DIM_ + tid + 256]  = d1 * inv * w[tid + 256] + b[tid + 256];
}

// ---------------- mma + cp.async helpers -------------------------------------
__device__ __forceinline__ void mma_tf32(
    float& c0, float& c1, float& c2, float& c3,
    uint32_t a0, uint32_t a1, uint32_t a2, uint32_t a3,
    uint32_t b0, uint32_t b1)
{
    asm volatile(
        "mma.sync.aligned.m16n8k8.row.col.f32.tf32.tf32.f32 "
        "{%0,%1,%2,%3}, {%4,%5,%6,%7}, {%8,%9}, {%0,%1,%2,%3};"
        : "+f"(c0), "+f"(c1), "+f"(c2), "+f"(c3)
        : "r"(a0), "r"(a1), "r"(a2), "r"(a3), "r"(b0), "r"(b1));
}
__device__ __forceinline__ void cpa16(void* dst, const void* src) {
    uint32_t d = (uint32_t)__cvta_generic_to_shared(dst);
    asm volatile("cp.async.cg.shared.global [%0], [%1], 16;" :: "r"(d), "l"(src));
}
#define CP_COMMIT() asm volatile("cp.async.commit_group;" ::: "memory")
#define CP_WAIT1()  asm volatile("cp.async.wait_group 1;" ::: "memory")
#define CP_WAIT0()  asm volatile("cp.async.wait_group 0;" ::: "memory")

#define BK2 16
#define RS  20      // [row][k] stride (words): frag banks 20g+tg = all 32 distinct

// ---------------- main mma GEMM: 128 threads, 2x2 warps, 64x64 warp tile -----
// BN=128: 3-stage single-sync pipeline, 2 CTAs/SM.
// BN=64 : 2-stage pipeline, 3 CTAs/SM (occupancy for small GEMMs).
// MODE 0: standard epilogue; MODE 1: qkv split; MODE 2: ctx layout;
// MODE 3: exp + atomic row sums (sim3).
// SPLITK: blockIdx.z = bh*4 + split, Kdim = chunk length.
template<int BM, int BN, bool TB, int MODE, bool SPLITK>
__global__ __launch_bounds__(128, (BN == 64) ? 3 : 2) void mma_gemm_kernel(
    const float* __restrict__ A, const float* __restrict__ B,
    float* __restrict__ C, int Ndim, int Kdim, int ldA, int ldB,
    long long sA, long long sB, long long sC,
    float alpha,
    const float* __restrict__ resid, float residScale,
    const float* __restrict__ residScalePtr,
    const float* __restrict__ bias)
{
    constexpr int MT = 4;               // 64 rows / 16
    constexpr int NT = BN / 16;         // (BN/2) / 8
    constexpr int RSB = BN + 8;         // [k][n] stride: frag banks 8tg+g distinct
    constexpr int ASZ = BM * RS;
    constexpr int BSZ = TB ? BN * RS : BK2 * RSB;
    constexpr int STG = ASZ + BSZ;
    constexpr int STAGES = (BN == 64) ? 2 : 3;

    extern __shared__ __align__(16) float smp[];

    int bz = blockIdx.z;
    long long aOff, bOff, cOff;
    if (SPLITK) {
        int bz0 = bz >> 2, sp = bz & 3;
        aOff = (long long)bz0 * sA + (long long)sp * Kdim;
        bOff = (long long)bz0 * sB + (long long)sp * Kdim * ldB;
        cOff = (long long)bz * sC;
    } else {
        aOff = (long long)bz * sA;
        bOff = (long long)bz * sB;
        cOff = (long long)bz * sC;
    }
    const float* Ab = A + aOff;
    const float* Bb = B + bOff;
    float*       Cb = C + cOff;
    const float* Rb = resid ? resid + cOff : nullptr;

    int n0 = blockIdx.x * BN;
    int m0 = blockIdx.y * BM;
    int tid  = threadIdx.x;
    int wid  = tid >> 5;
    int lane = tid & 31;
    int wm = wid >> 1, wn = wid & 1;
    int tm0 = wm * 64, tn0 = wn * (BN / 2);
    int g  = lane >> 2;
    int tg = lane & 3;

    float acc[MT][NT][4];
    #pragma unroll
    for (int i = 0; i < MT; i++)
        #pragma unroll
        for (int j = 0; j < NT; j++)
            #pragma unroll
            for (int c = 0; c < 4; c++) acc[i][j][c] = 0.f;

    auto loadTile = [&](int t, int st) {
        int k0 = t * BK2;
        float* As = smp + st * STG;
        float* Bs = As + ASZ;
        #pragma unroll
        for (int c = 0; c < BM / 32; c++) {
            int id = c * 128 + tid;
            int m = id >> 2, kq = (id & 3) * 4;
            cpa16(&As[m * RS + kq],
                  Ab + (long long)(m0 + m) * ldA + k0 + kq);
        }
        if (TB) {
            #pragma unroll
            for (int c = 0; c < BN / 32; c++) {
                int id = c * 128 + tid;
                int n = id >> 2, kq = (id & 3) * 4;
                cpa16(&Bs[n * RS + kq],
                      Bb + (long long)(n0 + n) * ldB + k0 + kq);
            }
        } else {
            constexpr int CPR = BN / 4;   // 16B chunks per k-row
            #pragma unroll
            for (int c = 0; c < BN / 32; c++) {
                int id = c * 128 + tid;
                int k = id / CPR, nq = (id % CPR) * 4;
                cpa16(&Bs[k * RSB + nq],
                      Bb + (long long)(k0 + k) * ldB + n0 + nq);
            }
        }
    };

    auto computeStage = [&](int st) {
        const float* as = smp + st * STG;
        const float* bs = as + ASZ;
        #pragma unroll
        for (int kk = 0; kk < BK2; kk += 8) {
            int c0 = kk + tg, c1 = c0 + 4;
            uint32_t af[MT][4], bf[NT][2];
            #pragma unroll
            for (int i = 0; i < MT; i++) {
                int r0 = (tm0 + i * 16 + g) * RS;
                int r1 = r0 + 8 * RS;
                af[i][0] = __float_as_uint(as[r0 + c0]);
                af[i][1] = __float_as_uint(as[r1 + c0]);
                af[i][2] = __float_as_uint(as[r0 + c1]);
                af[i][3] = __float_as_uint(as[r1 + c1]);
            }
            #pragma unroll
            for (int j = 0; j < NT; j++) {
                if (TB) {
                    int rn = (tn0 + j * 8 + g) * RS;
                    bf[j][0] = __float_as_uint(bs[rn + c0]);
                    bf[j][1] = __float_as_uint(bs[rn + c1]);
                } else {
                    int b0 = c0 * RSB + tn0 + j * 8 + g;
                    bf[j][0] = __float_as_uint(bs[b0]);
                    bf[j][1] = __float_as_uint(bs[b0 + 4 * RSB]);
                }
            }
            #pragma unroll
            for (int i = 0; i < MT; i++)
                #pragma unroll
                for (int j = 0; j < NT; j++)
                    mma_tf32(acc[i][j][0], acc[i][j][1], acc[i][j][2], acc[i][j][3],
                             af[i][0], af[i][1], af[i][2], af[i][3],
                             bf[j][0], bf[j][1]);
        }
    };

    int nIter = Kdim / BK2;
    loadTile(0, 0); CP_COMMIT();
    loadTile(1, 1); CP_COMMIT();
    int p = 0;
    if (STAGES == 3) {
        for (int t = 0; t < nIter; t++) {
            CP_WAIT1();
            __syncthreads();
            if (t + 2 < nIter) {
                int st = p + 2; if (st >= 3) st -= 3;
                loadTile(t + 2, st);
            }
            CP_COMMIT();
            computeStage(p);
            p = (p + 1 == 3) ? 0 : p + 1;
        }
    } else {
        for (int t = 0; t < nIter; t++) {
            CP_WAIT1();
            __syncthreads();
            computeStage(p);
            __syncthreads();
            if (t + 2 < nIter) loadTile(t + 2, p);
            CP_COMMIT();
            p ^= 1;
        }
    }

    // ---------------- epilogue ----------------
    if (MODE == 3) {
        #pragma unroll
        for (int i = 0; i < MT; i++) {
            int r0 = m0 + tm0 + i * 16 + g;
            int r1 = r0 + 8;
            float s0 = 0.f, s1 = 0.f;
            #pragma unroll
            for (int j = 0; j < NT; j++) {
                int cc = n0 + tn0 + j * 8 + tg * 2;
                float e0 = __expf(acc[i][j][0]);
                float e1 = __expf(acc[i][j][1]);
                float e2 = __expf(acc[i][j][2]);
                float e3 = __expf(acc[i][j][3]);
                *(float2*)(Cb + (long long)r0 * Ndim + cc) = make_float2(e0, e1);
                *(float2*)(Cb + (long long)r1 * Ndim + cc) = make_float2(e2, e3);
                s0 += e0 + e1; s1 += e2 + e3;
            }
            s0 += __shfl_xor_sync(0xffffffffu, s0, 1);
            s0 += __shfl_xor_sync(0xffffffffu, s0, 2);
            s1 += __shfl_xor_sync(0xffffffffu, s1, 1);
            s1 += __shfl_xor_sync(0xffffffffu, s1, 2);
            if (tg == 0) {
                atomicAdd(&g_rsum[bz * M_ + r0], s0);
                atomicAdd(&g_rsum[bz * M_ + r1], s1);
            }
        }
        return;
    }

    float rs = residScalePtr ? *residScalePtr : residScale;
    #pragma unroll
    for (int i = 0; i < MT; i++) {
        int r0 = m0 + tm0 + i * 16 + g;
        int r1 = r0 + 8;
        #pragma unroll
        for (int j = 0; j < NT; j++) {
            int cc = n0 + tn0 + j * 8 + tg * 2;
            if (MODE == 0) {
                float2 bv = bias ? *(const float2*)(bias + cc) : make_float2(0.f, 0.f);
                float2 v0 = make_float2(alpha * acc[i][j][0] + bv.x,
                                        alpha * acc[i][j][1] + bv.y);
                float2 v1 = make_float2(alpha * acc[i][j][2] + bv.x,
                                        alpha * acc[i][j][3] + bv.y);
                if (Rb) {
                    float2 q0 = *(const float2*)(Rb + (long long)r0 * Ndim + cc);
                    float2 q1 = *(const float2*)(Rb + (long long)r1 * Ndim + cc);
                    v0.x += rs * q0.x; v0.y += rs * q0.y;
                    v1.x += rs * q1.x; v1.y += rs * q1.y;
                }
                *(float2*)(Cb + (long long)r0 * Ndim + cc) = v0;
                *(float2*)(Cb + (long long)r1 * Ndim + cc) = v1;
            } else if (MODE == 1) {
                int which = cc >> 9;
                int hc = cc & 511;
                int h = hc >> 6, d = hc & 63;
                float sc = (which == 0) ? 0.125f : 1.0f;
                float* dstbuf = (which == 0) ? g_q : (which == 1) ? g_k : g_v;
                #pragma unroll
                for (int rr = 0; rr < 2; rr++) {
                    int row = rr ? r1 : r0;
                    int b = row >> 12, nn = row & 4095;
                    long long dst = (((long long)((b << 3) + h)) * N_ + nn) * DH_ + d;
                    float2 v = rr ? make_float2(sc * acc[i][j][2], sc * acc[i][j][3])
                                  : make_float2(sc * acc[i][j][0], sc * acc[i][j][1]);
                    *(float2*)(dstbuf + dst) = v;
                }
            } else {
                int b = bz >> 3, h = bz & 7;
                *(float2*)(g_ctx + ((long long)(b * N_ + r0)) * DIM_ + h * DH_ + cc) =
                    make_float2(acc[i][j][0], acc[i][j][1]);
                *(float2*)(g_ctx + ((long long)(b * N_ + r1)) * DIM_ + h * DH_ + cc) =
                    make_float2(acc[i][j][2], acc[i][j][3]);
            }
        }
    }
}

// ---------------- sim GEMM (TB) with fused full-row softmax ------------------
__global__ __launch_bounds__(256) void sim_softmax_kernel(
    const float* __restrict__ A, const float* __restrict__ Bm,
    float* __restrict__ C, int Kdim,
    long long sA, long long sB, long long sC)
{
    constexpr int BMs = 64;
    __shared__ __align__(16) float As[BMs * RS];
    __shared__ __align__(16) float Bs[256 * RS];
    __shared__ float redM[4][BMs];
    __shared__ float redS[4][BMs];

    int bz = blockIdx.z;
    const float* Ab = A + (long long)bz * sA;
    const float* Bb = Bm + (long long)bz * sB;
    float*       Cb = C + (long long)bz * sC;

    int m0 = blockIdx.y * BMs;
    int tid  = threadIdx.x;
    int wid  = tid >> 5;
    int lane = tid & 31;
    int wm = wid >> 2, wn = wid & 3;
    int tm0 = wm * 32, tn0 = wn * 64;
    int g  = lane >> 2;
    int tg = lane & 3;

    float acc[2][8][4];
    #pragma unroll
    for (int i = 0; i < 2; i++)
        #pragma unroll
        for (int j = 0; j < 8; j++)
            #pragma unroll
            for (int c = 0; c < 4; c++) acc[i][j][c] = 0.f;

    for (int k0 = 0; k0 < Kdim; k0 += BK2) {
        {
            int m = tid >> 2, kq = (tid & 3) * 4;
            cpa16(&As[m * RS + kq], Ab + (long long)(m0 + m) * Kdim + k0 + kq);
        }
        #pragma unroll
        for (int c = 0; c < 4; c++) {
            int id = c * 256 + tid;
            int n = id >> 2, kq = (id & 3) * 4;
            cpa16(&Bs[n * RS + kq], Bb + (long long)n * Kdim + k0 + kq);
        }
        CP_COMMIT();
        CP_WAIT0();
        __syncthreads();

        #pragma unroll
        for (int kk = 0; kk < BK2; kk += 8) {
            int c0 = kk + tg, c1 = c0 + 4;
            uint32_t af[2][4], bf[8][2];
            #pragma unroll
            for (int i = 0; i < 2; i++) {
                int r0 = (tm0 + i * 16 + g) * RS;
                int r1 = r0 + 8 * RS;
                af[i][0] = __float_as_uint(As[r0 + c0]);
                af[i][1] = __float_as_uint(As[r1 + c0]);
                af[i][2] = __float_as_uint(As[r0 + c1]);
                af[i][3] = __float_as_uint(As[r1 + c1]);
            }
            #pragma unroll
            for (int j = 0; j < 8; j++) {
                int rn = (tn0 + j * 8 + g) * RS;
                bf[j][0] = __float_as_uint(Bs[rn + c0]);
                bf[j][1] = __float_as_uint(Bs[rn + c1]);
            }
            #pragma unroll
            for (int i = 0; i < 2; i++)
                #pragma unroll
                for (int j = 0; j < 8; j++)
                    mma_tf32(acc[i][j][0], acc[i][j][1], acc[i][j][2], acc[i][j][3],
                             af[i][0], af[i][1], af[i][2], af[i][3],
                             bf[j][0], bf[j][1]);
        }
        __syncthreads();
    }

    #pragma unroll
    for (int i = 0; i < 2; i++) {
        float mx0 = -1e30f, mx1 = -1e30f;
        #pragma unroll
        for (int j = 0; j < 8; j++) {
            mx0 = fmaxf(mx0, fmaxf(acc[i][j][0], acc[i][j][1]));
            mx1 = fmaxf(mx1, fmaxf(acc[i][j][2], acc[i][j][3]));
        }
        mx0 = fmaxf(mx0, __shfl_xor_sync(0xffffffffu, mx0, 1));
        mx0 = fmaxf(mx0, __shfl_xor_sync(0xffffffffu, mx0, 2));
        mx1 = fmaxf(mx1, __shfl_xor_sync(0xffffffffu, mx1, 1));
        mx1 = fmaxf(mx1, __shfl_xor_sync(0xffffffffu, mx1, 2));
        if (tg == 0) {
            redM[wn][tm0 + i * 16 + g]     = mx0;
            redM[wn][tm0 + i * 16 + g + 8] = mx1;
        }
    }
    __syncthreads();
    #pragma unroll
    for (int i = 0; i < 2; i++) {
        int rb0 = tm0 + i * 16 + g, rb1 = rb0 + 8;
        float mx0 = fmaxf(fmaxf(redM[0][rb0], redM[1][rb0]),
                          fmaxf(redM[2][rb0], redM[3][rb0]));
        float mx1 = fmaxf(fmaxf(redM[0][rb1], redM[1][rb1]),
                          fmaxf(redM[2][rb1], redM[3][rb1]));
        float s0 = 0.f, s1 = 0.f;
        #pragma unroll
        for (int j = 0; j < 8; j++) {
            float e0 = __expf(acc[i][j][0] - mx0);
            float e1 = __expf(acc[i][j][1] - mx0);
            float e2 = __expf(acc[i][j][2] - mx1);
            float e3 = __expf(acc[i][j][3] - mx1);
            acc[i][j][0] = e0; acc[i][j][1] = e1;
            acc[i][j][2] = e2; acc[i][j][3] = e3;
            s0 += e0 + e1; s1 += e2 + e3;
        }
        s0 += __shfl_xor_sync(0xffffffffu, s0, 1);
        s0 += __shfl_xor_sync(0xffffffffu, s0, 2);
        s1 += __shfl_xor_sync(0xffffffffu, s1, 1);
        s1 += __shfl_xor_sync(0xffffffffu, s1, 2);
        if (tg == 0) { redS[wn][rb0] = s0; redS[wn][rb1] = s1; }
    }
    __syncthreads();
    #pragma unroll
    for (int i = 0; i < 2; i++) {
        int rb0 = tm0 + i * 16 + g, rb1 = rb0 + 8;
        float i0 = 1.f / (redS[0][rb0] + redS[1][rb0] + redS[2][rb0] + redS[3][rb0]);
        float i1 = 1.f / (redS[0][rb1] + redS[1][rb1] + redS[2][rb1] + redS[3][rb1]);
        int r0 = m0 + rb0, r1 = m0 + rb1;
        #pragma unroll
        for (int j = 0; j < 8; j++) {
            int cc = tn0 + j * 8 + tg * 2;
            *(float2*)(Cb + (long long)r0 * 256 + cc) =
                make_float2(acc[i][j][0] * i0, acc[i][j][1] * i0);
            *(float2*)(Cb + (long long)r1 * 256 + cc) =
                make_float2(acc[i][j][2] * i1, acc[i][j][3] * i1);
        }
    }
}

// ---------------- landmark means ---------------------------------------------
__global__ __launch_bounds__(256) void landmark_kernel()
{
    int id = blockIdx.x * 256 + threadIdx.x;
    const int half = BH_ * M_ * DH_;
    bool isK = id >= half;
    int t = isK ? id - half : id;
    int d  = t & 63;
    int m  = (t >> 6) & 255;
    int bh = t >> 14;
    const float* src = (isK ? g_k : g_q) + ((long long)bh * N_ + m * L_) * DH_ + d;
    float s = 0.f;
    #pragma unroll
    for (int l = 0; l < L_; l++) s += src[l * DH_];
    (isK ? g_kl : g_ql)[t] = s * (1.0f / L_);
}

// ---------------- zero rsum + max scratch ------------------------------------
__global__ __launch_bounds__(256) void zero_scratch_kernel()
{
    int id = blockIdx.x * 256 + threadIdx.x;
    g_rsum[id] = 0.f;
    if (id < 2) g_max[id] = 0.f;
}

// ---------------- a3v split-K reduce + row normalize -------------------------
__global__ __launch_bounds__(256) void a3v_reduce_kernel()
{
    int idx = blockIdx.x * 256 + threadIdx.x;
    int rrow = idx >> 6;
    int bh = idx >> 14;
    int inner = idx & 16383;
    long long base = (long long)bh * 4 * 16384 + inner;
    float s = g_part[base] + g_part[base + 16384]
            + g_part[base + 2 * 16384] + g_part[base + 3 * 16384];
    g_a3v[idx] = s / g_rsum[rrow];
}

// ---------------- pinv init ---------------------------------------------------
__global__ __launch_bounds__(256) void pinv_absmax_kernel()
{
    __shared__ float sh[256];
    const float* X = g_a2 + (long long)blockIdx.x * (M_ * M_);
    int tid = threadIdx.x;
    float cs = 0.f, rs = 0.f;
    for (int j = 0; j < M_; j++) cs += fabsf(X[tid * M_ + j]);
    for (int i = 0; i < M_; i++) rs += fabsf(X[i * M_ + tid]);
    float cm = blockReduceMax(cs, sh);
    float rm = blockReduceMax(rs, sh);
    if (tid == 0) {
        atomicMax(reinterpret_cast<int*>(&g_max[0]), __float_as_int(cm));
        atomicMax(reinterpret_cast<int*>(&g_max[1]), __float_as_int(rm));
    }
}

__global__ __launch_bounds__(256) void zinit_kernel()
{
    long long id = (long long)blockIdx.x * 256 + threadIdx.x;
    float inv = 1.0f / (g_max[0] * g_max[1]);
    long long bh = id >> 16;
    int rem = (int)(id & 65535);
    int row = rem >> 8, col = rem & 255;
    g_z0[id] = g_a2[bh * (M_ * M_) + (long long)col * M_ + row] * inv;
}

// ---------------- depthwise conv residual added into ctx (smem tiled) ---------
__global__ __launch_bounds__(256) void conv_add_kernel(const float* __restrict__ cw)
{
    __shared__ __align__(16) float sv[160 * 64];

    int bid = blockIdx.x;
    int bh = bid >> 5;
    int tile = bid & 31;
    int n0 = tile * 128;
    int h = bh & 7, b = bh >> 3;
    int tid = threadIdx.x;
    const float* vb = g_v + ((long long)bh << 18);

    #pragma unroll
    for (int c = 0; c < 10; c++) {
        int e = (c * 256 + tid) * 4;
        int r = e >> 6, d = e & 63;
        int gr = n0 - 16 + r;
        float4 val = make_float4(0.f, 0.f, 0.f, 0.f);
        if ((unsigned)gr < (unsigned)N_)
            val = *(const float4*)(vb + (long long)gr * DH_ + d);
        *(float4*)(sv + r * 64 + d) = val;
    }
    __syncthreads();

    int d = tid & 63, rg = tid >> 6;
    float wr[33];
    #pragma unroll
    for (int k = 0; k < 33; k++) wr[k] = cw[h * 33 + k];

    #pragma unroll
    for (int half = 0; half < 2; half++) {
        int ob = rg * 32 + half * 16;
        float in[48];
        #pragma unroll
        for (int j = 0; j < 48; j++) in[j] = sv[(ob + j) * 64 + d];
        #pragma unroll
        for (int i = 0; i < 16; i++) {
            float acc = 0.f;
            #pragma unroll
            for (int k = 0; k < 33; k++) acc += wr[k] * in[i + k];
            int grow = n0 + ob + i;
            g_ctx[((long long)(b * N_ + grow)) * DIM_ + h * DH_ + d] += acc;
        }
    }
}

// ---------------- host helpers -------------------------------------------------
static float* symaddr(const void* sym) {
    void* p = nullptr;
    cudaGetSymbolAddress(&p, sym);
    return (float*)p;
}

template<int BM, int BN, bool TB, int MODE, bool SPLITK>
static void launch_gemm(dim3 grid,
                 const float* A, const float* B, float* C,
                 int N, int K, int ldA, int ldB,
                 long long sA, long long sB, long long sC,
                 float alpha, const float* resid, float rs,
                 const float* rsPtr, const float* bias)
{
    constexpr int RSB = BN + 8;
    constexpr int ASZ = BM * RS;
    constexpr int BSZ = TB ? BN * RS : BK2 * RSB;
    constexpr int STAGES = (BN == 64) ? 2 : 3;
    int smem = STAGES * (ASZ + BSZ) * 4;
    auto kfn = mma_gemm_kernel<BM, BN, TB, MODE, SPLITK>;
    cudaFuncSetAttribute(kfn, cudaFuncAttributeMaxDynamicSharedMemorySize, smem);
    kfn<<<grid, 128, smem>>>(A, B, C, N, K, ldA, ldB, sA, sB, sC,
                             alpha, resid, rs, rsPtr, bias);
}

template<int MODE>
static void gemm(const float* A, const float* B, float* C,
                 int M, int N, int K, int batch, int ldA, int ldB,
                 long long sA, long long sB, long long sC, bool tb,
                 float alpha = 1.f,
                 const float* resid = nullptr, float rs = 0.f,
                 const float* rsPtr = nullptr,
                 const float* bias = nullptr,
                 bool forceBN64 = false)
{
    if (N % 128 == 0 && !forceBN64) {
        dim3 grid(N / 128, M / 128, batch);
        if (tb)
            launch_gemm<128, 128, true , MODE, false>(grid, A, B, C, N, K,
                ldA, ldB, sA, sB, sC, alpha, resid, rs, rsPtr, bias);
        else
            launch_gemm<128, 128, false, MODE, false>(grid, A, B, C, N, K,
                ldA, ldB, sA, sB, sC, alpha, resid, rs, rsPtr, bias);
    } else {
        dim3 grid(N / 64, M / 128, batch);
        if (tb)
            launch_gemm<128, 64, true , MODE, false>(grid, A, B, C, N, K,
                ldA, ldB, sA, sB, sC, alpha, resid, rs, rsPtr, bias);
        else
            launch_gemm<128, 64, false, MODE, false>(grid, A, B, C, N, K,
                ldA, ldB, sA, sB, sC, alpha, resid, rs, rsPtr, bias);
    }
}

extern "C" void kernel_launch(void* const* d_in, const int* in_sizes, int n_in,
                              void* d_out, int out_size)
{
    const float* x      = (const float*)d_in[0];
    const float* ln_w   = (const float*)d_in[1];
    const float* ln_b   = (const float*)d_in[2];
    const float* w_qkv  = (const float*)d_in[3];
    const float* w_out  = (const float*)d_in[4];
    const float* b_out  = (const float*)d_in[5];
    const float* conv_w = (const float*)d_in[6];
    const float* omega  = (const float*)d_in[7];
    float* out = (float*)d_out;

    float* p_ln   = symaddr(g_ln);
    float* p_q    = symaddr(g_q);
    float* p_k    = symaddr(g_k);
    float* p_v    = symaddr(g_v);
    float* p_ql   = symaddr(g_ql);
    float* p_kl   = symaddr(g_kl);
    float* p_a1   = symaddr(g_a1);
    float* p_a3   = symaddr(g_a3);
    float* p_a2   = symaddr(g_a2);
    float* p_z0   = symaddr(g_z0);
    float* p_z1   = symaddr(g_z1);
    float* p_t1   = symaddr(g_t1);
    float* p_t2   = symaddr(g_t2);
    float* p_t3   = symaddr(g_t3);
    float* p_a3v  = symaddr(g_a3v);
    float* p_w    = symaddr(g_w);
    float* p_part = symaddr(g_part);
    float* p_ctx  = symaddr(g_ctx);

    const long long sQ  = (long long)N_ * DH_;
    const long long sL  = (long long)M_ * DH_;
    const long long sS1 = (long long)N_ * M_;
    const long long sA2 = (long long)M_ * M_;

    // 1) layernorm
    ln_kernel<<<ROWS_, 256>>>(x, ln_w, ln_b);

    // 2) qkv projection, epilogue writes q (scaled), k, v head-major
    gemm<1>(p_ln, w_qkv, nullptr, ROWS_, 3 * DIM_, DIM_, 1, DIM_, 3 * DIM_,
            0, 0, 0, false);

    // 3) landmarks
    landmark_kernel<<<(2 * BH_ * M_ * DH_) / 256, 256>>>();

    // 4) sim1 + softmax -> a1; sim2 + softmax -> a2
    sim_softmax_kernel<<<dim3(1, N_ / 64, BH_), 256>>>(
        p_q, p_kl, p_a1, DH_, sQ, sL, sS1);
    sim_softmax_kernel<<<dim3(1, M_ / 64, BH_), 256>>>(
        p_ql, p_kl, p_a2, DH_, sL, sL, sA2);

    // 5) sim3 -> exp(sim3) with fused row sums
    zero_scratch_kernel<<<(BH_ * M_) / 256, 256>>>();
    gemm<3>(p_ql, p_k, p_a3, M_, N_, DH_, BH_, DH_, DH_, sL, sQ, sS1, true);

    // 6) Moore-Penrose pinv of a2 (Newton-Schulz, 6 iters), BN=64, 3 CTAs/SM
    pinv_absmax_kernel<<<BH_, 256>>>();
    zinit_kernel<<<(BH_ * M_ * M_) / 256, 256>>>();

    for (int it = 0; it < 6; it++) {
        float* zin  = (it & 1) ? p_z1 : p_z0;
        float* zout = (it & 1) ? p_z0 : p_z1;
        gemm<0>(p_a2, zin, p_t1, M_, M_, M_, BH_, M_, M_, sA2, sA2, sA2, false,
                1.f, nullptr, 0.f, nullptr, nullptr, true);
        gemm<0>(p_t1, p_t1, p_t2, M_, M_, M_, BH_, M_, M_, sA2, sA2, sA2, false,
                -1.f, p_t1, 7.f, nullptr, nullptr, true);
        gemm<0>(p_t1, p_t2, p_t3, M_, M_, M_, BH_, M_, M_, sA2, sA2, sA2, false,
                -1.f, p_t1, 15.f, nullptr, nullptr, true);
        gemm<0>(zin, p_t3, zout, M_, M_, M_, BH_, M_, M_, sA2, sA2, sA2, false,
                -0.25f, zin, 3.25f, nullptr, nullptr, true);
    }

    // 7) a3v = (exp(sim3) @ v) / rowsum, split-K x4
    {
        dim3 grid(1, M_ / 128, BH_ * 4);
        launch_gemm<128, 64, false, 0, true>(grid, p_a3, p_v, p_part,
            DH_, N_ / 4, N_, DH_, sS1, sQ, sL,
            1.f, nullptr, 0.f, nullptr, nullptr);
        a3v_reduce_kernel<<<(BH_ * M_ * DH_) / 256, 256>>>();
    }

    // 8) w = a2inv @ a3v  (tiny: 256x64x256)
    gemm<0>(p_z0, p_a3v, p_w, M_, DH_, M_, BH_, M_, DH_, sA2, sL, sL, false);

    // 9) ctx = a1 @ w  (reassociated; writes ctx layout directly)
    gemm<2>(p_a1, p_w, nullptr, N_, DH_, M_, BH_, M_, DH_, sS1, sL, 0, false);

    // 10) depthwise conv residual added into ctx (smem tiled)
    conv_add_kernel<<<BH_ * (N_ / 128), 256>>>(conv_w);

    // 11) output projection + bias + omega * x
    gemm<0>(p_ctx, w_out, out, ROWS_, DIM_, DIM_, 1, DIM_, DIM_, 0, 0, 0, false,
            1.f, x, 0.f, omega, b_out);
}